// round 16
// baseline (speedup 1.0000x reference)
#include <cuda_runtime.h>
#include <cuda_fp16.h>
#include <mma.h>
#include <math.h>
#include <stdint.h>

using namespace nvcuda;

#define Bc 2
#define Lc 1024
#define Dc 1024
#define Hc 16
#define HDc 64
#define FFc 4096
#define NLc 8
#define Mtot (Bc*Lc)

// ---------------- scratch (device globals; no allocation) ----------------
__device__ float g_x   [Mtot*Dc];
__device__ float g_tmp [Mtot*Dc];
__device__ float g_tmp2[Mtot*Dc];
__device__ float g_pe  [Lc*HDc];
__device__ float g_bqkv[NLc*3*Dc];

__device__ __half g_xh [Mtot*Dc];
__device__ __half g_qh [Mtot*Dc];
__device__ __half g_kh [Mtot*Dc];
__device__ __half g_vh [Mtot*Dc];
__device__ __half g_oh [Mtot*Dc];
__device__ __half g_ffh[(size_t)Mtot*FFc];
__device__ __half g_wqkv[(size_t)NLc*3*Dc*Dc];
__device__ __half g_wo [(size_t)NLc*Dc*Dc];
__device__ __half g_w1 [(size_t)NLc*Dc*FFc];
__device__ __half g_w2 [(size_t)NLc*FFc*Dc];

__device__ __forceinline__ float gelu_exact(float x) {
    return 0.5f * x * (1.0f + erff(x * 0.70710678118654752f));
}
__device__ __forceinline__ void cp_async16(uint32_t saddr, const void* gaddr) {
    asm volatile("cp.async.cg.shared.global [%0], [%1], 16;" :: "r"(saddr), "l"(gaddr));
}
__device__ __forceinline__ uint32_t smem_u32(const void* p) {
    uint32_t a;
    asm("{ .reg .u64 t; cvta.to.shared.u64 t, %1; cvt.u32.u64 %0, t; }" : "=r"(a) : "l"(p));
    return a;
}

// ================= 128x128 wmma GEMM core (8 warps, 64x32, BK64, 2-stage) =================
#define BKc 64
#define LDS 72
#define GEMM_DSM (4*128*LDS*2)   // 73728 B; C tile (67584) aliases where staged

#define GEMM_MAINLOOP_CORE(Ap, Bp, Kc, ld)                                                         \
    __half (*As)[128][LDS] = (__half (*)[128][LDS])dsm;                                            \
    __half (*Bs)[128][LDS] = (__half (*)[128][LDS])(dsm + 2 * 128 * LDS * 2);                      \
    const int tid = threadIdx.x;                                                                   \
    const int w = tid >> 5;                                                                        \
    const int wm = w & 1;                                                                          \
    const int wn = w >> 1;                                                                         \
    const int row0 = blockIdx.y * 128, col0 = blockIdx.x * 128;                                    \
    wmma::fragment<wmma::accumulator, 16, 16, 16, float> acc[4][2];                                \
    _Pragma("unroll")                                                                              \
    for (int i = 0; i < 4; i++)                                                                    \
        _Pragma("unroll")                                                                          \
        for (int j = 0; j < 2; j++) wmma::fill_fragment(acc[i][j], 0.0f);                          \
    const int nch = (Kc) / BKc;                                                                    \
    auto issue_chunk = [&](int buf, int c0) {                                                      \
        _Pragma("unroll")                                                                          \
        for (int i = 0; i < 4; i++) {                                                              \
            int s = tid + i * 256;                                                                 \
            int r = s >> 3, cc = (s & 7) * 8;                                                      \
            cp_async16(smem_u32(&As[buf][r][cc]), (Ap) + (size_t)(row0 + r) * (ld) + c0 + cc);     \
            cp_async16(smem_u32(&Bs[buf][r][cc]), (Bp) + (size_t)(col0 + r) * (ld) + c0 + cc);     \
        }                                                                                          \
        asm volatile("cp.async.commit_group;" ::: "memory");                                       \
    };                                                                                             \
    issue_chunk(0, 0);                                                                             \
    for (int c = 0; c < nch; c++) {                                                                \
        const int buf = c & 1;                                                                     \
        if (c + 1 < nch) {                                                                         \
            issue_chunk(buf ^ 1, (c + 1) * BKc);                                                   \
            asm volatile("cp.async.wait_group 1;" ::: "memory");                                   \
        } else {                                                                                   \
            asm volatile("cp.async.wait_group 0;" ::: "memory");                                   \
        }                                                                                          \
        __syncthreads();                                                                           \
        _Pragma("unroll")                                                                          \
        for (int kk = 0; kk < 4; kk++) {                                                           \
            wmma::fragment<wmma::matrix_a, 16, 16, 16, __half, wmma::row_major> af[4];             \
            wmma::fragment<wmma::matrix_b, 16, 16, 16, __half, wmma::col_major> bf[2];             \
            _Pragma("unroll")                                                                      \
            for (int i = 0; i < 4; i++)                                                            \
                wmma::load_matrix_sync(af[i], &As[buf][wm * 64 + i * 16][kk * 16], LDS);           \
            _Pragma("unroll")                                                                      \
            for (int j = 0; j < 2; j++)                                                            \
                wmma::load_matrix_sync(bf[j], &Bs[buf][wn * 32 + j * 16][kk * 16], LDS);           \
            _Pragma("unroll")                                                                      \
            for (int i = 0; i < 4; i++)                                                            \
                _Pragma("unroll")                                                                  \
                for (int j = 0; j < 2; j++)                                                        \
                    wmma::mma_sync(acc[i][j], af[i], bf[j], acc[i][j]);                            \
        }                                                                                          \
        __syncthreads();                                                                           \
    }

#define GEMM_STAGE_C()                                                                             \
    float* Cs = (float*)dsm;                                                                       \
    _Pragma("unroll")                                                                              \
    for (int i = 0; i < 4; i++)                                                                    \
        _Pragma("unroll")                                                                          \
        for (int j = 0; j < 2; j++)                                                                \
            wmma::store_matrix_sync(Cs + (size_t)(wm * 64 + i * 16) * 132 + wn * 32 + j * 16,      \
                                    acc[i][j], 132, wmma::mem_row_major);                          \
    __syncthreads();

// ---- FF1 GEMM: f16 gelu(+bias) ----
__global__ __launch_bounds__(256) void gemm_g(
    const __half* __restrict__ A, const __half* __restrict__ Bt,
    const float* __restrict__ bias, __half* __restrict__ Ch, int M, int N, int K)
{
    extern __shared__ char dsm[];
    GEMM_MAINLOOP_CORE(A, Bt, K, K)
    GEMM_STAGE_C()

#pragma unroll
    for (int it = 0; it < 16; it++) {
        int vlin = tid + it * 256;
        int row = vlin >> 5;
        int vc = (vlin & 31) * 4;
        float4 v = *(float4*)(Cs + (size_t)row * 132 + vc);
        float4 b = *(const float4*)(bias + col0 + vc);
        v.x = gelu_exact(v.x + b.x); v.y = gelu_exact(v.y + b.y);
        v.z = gelu_exact(v.z + b.z); v.w = gelu_exact(v.w + b.w);
        size_t gidx = (size_t)(row0 + row) * N + col0 + vc;
        *(__half2*)(Ch + gidx)     = __floats2half2_rn(v.x, v.y);
        *(__half2*)(Ch + gidx + 2) = __floats2half2_rn(v.z, v.w);
    }
}

// ---- split-K GEMM (z in {0,1}): direct fragment store to fp32 partial buffer ----
__global__ __launch_bounds__(256) void gemm_s(
    const __half* __restrict__ A, const __half* __restrict__ Bt,
    float* __restrict__ Cf0, float* __restrict__ Cf1, int N, int Kh, int ld)
{
    extern __shared__ char dsm[];
    const int z = blockIdx.z;
    const __half* Ap = A  + z * Kh;
    const __half* Bp = Bt + z * Kh;
    GEMM_MAINLOOP_CORE(Ap, Bp, Kh, ld)

    float* Cf = z ? Cf1 : Cf0;
#pragma unroll
    for (int i = 0; i < 4; i++)
#pragma unroll
        for (int j = 0; j < 2; j++)
            wmma::store_matrix_sync(
                Cf + (size_t)(row0 + wm * 64 + i * 16) * N + col0 + wn * 32 + j * 16,
                acc[i][j], N, wmma::mem_row_major);
}

// ---- QKV GEMM with fused bias + RoPE + fp16 convert epilogue ----
__global__ __launch_bounds__(256) void gemm_qkv(
    const __half* __restrict__ A, const __half* __restrict__ Bt,
    const float* __restrict__ bias, const float* __restrict__ pe,
    __half* __restrict__ qh, __half* __restrict__ kh, __half* __restrict__ vh,
    int M, int N, int K)
{
    extern __shared__ char dsm[];
    GEMM_MAINLOOP_CORE(A, Bt, K, K)
    GEMM_STAGE_C()

#pragma unroll
    for (int it = 0; it < 16; it++) {
        int vlin = tid + it * 256;
        int row = vlin >> 5;
        int vc = (vlin & 31) * 4;
        float4 v = *(float4*)(Cs + (size_t)row * 132 + vc);
        float4 b = *(const float4*)(bias + col0 + vc);
        v.x += b.x; v.y += b.y; v.z += b.z; v.w += b.w;

        const int grow = row0 + row;
        const int gcol = col0 + vc;
        if (gcol < 2 * Dc) {
            const int l = grow & (Lc - 1);
            const int d = gcol & 63;
            const int head = (gcol & 1023) >> 6;
            const int j = d >> 1;
            float4 p4 = *(const float4*)(pe + l * 64 + d);
            float e1 = v.x * p4.x - v.y * p4.y;
            float o1 = v.x * p4.y + v.y * p4.x;
            float e2 = v.z * p4.z - v.w * p4.w;
            float o2 = v.z * p4.w + v.w * p4.z;
            __half* dst;
            if (gcol < Dc) {
                e1 *= 0.125f; o1 *= 0.125f; e2 *= 0.125f; o2 *= 0.125f;
                dst = qh;
            } else {
                dst = kh;
            }
            size_t base = (size_t)grow * Dc + head * 64;
            *(__half2*)(dst + base + j)      = __floats2half2_rn(e1, e2);
            *(__half2*)(dst + base + 32 + j) = __floats2half2_rn(o1, o2);
        } else {
            size_t gidx = (size_t)grow * Dc + (gcol - 2 * Dc);
            *(__half2*)(vh + gidx)     = __floats2half2_rn(v.x, v.y);
            *(__half2*)(vh + gidx + 2) = __floats2half2_rn(v.z, v.w);
        }
    }
}

// ================= flash attention v3: 64-row Q tile, m8n32k16, 3 CTAs/SM =================
// smem: Q 9216 | K 2x9216 | V 2x9216 | S strips 8x2304 | P strips 8x1024 = 72704 B
#define FA_Q   0
#define FA_K   9216
#define FA_V   27648
#define FA_S   46080
#define FA_P   64512
#define FA_DSM 72704
__global__ __launch_bounds__(256) void fa_k(
    const __half* __restrict__ q, const __half* __restrict__ k,
    const __half* __restrict__ v, __half* __restrict__ o)
{
    extern __shared__ char dsm[];
    __half* Qs = (__half*)(dsm + FA_Q);
    __half* Kb = (__half*)(dsm + FA_K);
    __half* Vb = (__half*)(dsm + FA_V);

    const int tid = threadIdx.x;
    const int w = tid >> 5, lane = tid & 31;
    const int bh = blockIdx.y;
    const int b = bh >> 4, h = bh & 15;
    const int i0 = blockIdx.x * 64;
    const float slope = exp2f(-0.5f * (float)h);

    float* Ssw = (float*)(dsm + FA_S) + w * 8 * 72;
    __half* Psw = (__half*)(dsm + FA_P) + w * 8 * 64;

    // load Q tile (64 x 64 -> ld 72)
#pragma unroll
    for (int i = 0; i < 2; i++) {
        int s = tid + i * 256;
        int r = s >> 3, u = (s & 7) * 8;
        *(uint4*)(Qs + r * 72 + u) = *(const uint4*)(q + (size_t)(b * Lc + i0 + r) * Dc + h * 64 + u);
    }

    auto issue_kv = [&](int buf, int j0) {
        __half* kd = Kb + buf * 64 * 72;
        __half* vd = Vb + buf * 64 * 72;
#pragma unroll
        for (int i = 0; i < 2; i++) {
            int s = tid + i * 256;
            int r = s >> 3, u = (s & 7) * 8;
            cp_async16(smem_u32(kd + r * 72 + u), k + (size_t)(b * Lc + j0 + r) * Dc + h * 64 + u);
            cp_async16(smem_u32(vd + r * 72 + u), v + (size_t)(b * Lc + j0 + r) * Dc + h * 64 + u);
        }
        asm volatile("cp.async.commit_group;" ::: "memory");
    };

    const int rr = lane >> 2;            // 8 rows, 4 lanes each
    const int c0 = (lane & 3) * 16;      // 16 cols per lane
    const int i_abs = i0 + w * 8 + rr;

    float Oreg[16];
#pragma unroll
    for (int c = 0; c < 16; c++) Oreg[c] = 0.0f;
    float m_st = -1e30f, l_st = 0.0f;

    issue_kv(0, 0);
    __syncthreads();

    for (int jt = 0; jt < Lc / 64; jt++) {
        const int buf = jt & 1;
        const int j0 = jt * 64;
        if (jt + 1 < Lc / 64) {
            issue_kv(buf ^ 1, j0 + 64);
            asm volatile("cp.async.wait_group 1;" ::: "memory");
        } else {
            asm volatile("cp.async.wait_group 0;" ::: "memory");
        }
        __syncthreads();

        const __half* kd = Kb + buf * 64 * 72;
        const __half* vd = Vb + buf * 64 * 72;

        // S = Q(8x64) @ K^T(64x64) via m8n32k16, 2 n-fragments
        {
            wmma::fragment<wmma::matrix_a, 8, 32, 16, __half, wmma::row_major> af[4];
#pragma unroll
            for (int kk = 0; kk < 4; kk++)
                wmma::load_matrix_sync(af[kk], Qs + (w * 8) * 72 + kk * 16, 72);
#pragma unroll
            for (int n = 0; n < 2; n++) {
                wmma::fragment<wmma::accumulator, 8, 32, 16, float> cfr;
                wmma::fill_fragment(cfr, 0.0f);
#pragma unroll
                for (int kk = 0; kk < 4; kk++) {
                    wmma::fragment<wmma::matrix_b, 8, 32, 16, __half, wmma::col_major> bf;
                    wmma::load_matrix_sync(bf, kd + (n * 32) * 72 + kk * 16, 72);
                    wmma::mma_sync(cfr, af[kk], bf, cfr);
                }
                wmma::store_matrix_sync(Ssw + n * 32, cfr, 72, wmma::mem_row_major);
            }
        }
        __syncwarp();

        // online softmax: lane quad per row, 16 cols each
        {
            float s[16];
            float mx = -1e30f;
#pragma unroll
            for (int c = 0; c < 16; c++) {
                int j_abs = j0 + c0 + c;
                float bias = (i_abs > j_abs) ? slope * (float)(i_abs - j_abs) : 0.0f;
                s[c] = Ssw[rr * 72 + c0 + c] + bias;
                mx = fmaxf(mx, s[c]);
            }
            mx = fmaxf(mx, __shfl_xor_sync(0xffffffffu, mx, 1));
            mx = fmaxf(mx, __shfl_xor_sync(0xffffffffu, mx, 2));
            float m_new = fmaxf(m_st, mx);
            float factor = __expf(m_st - m_new);
            float sum = 0.0f;
#pragma unroll
            for (int c = 0; c < 16; c += 2) {
                float p0 = __expf(s[c] - m_new);
                float p1 = __expf(s[c + 1] - m_new);
                sum += p0 + p1;
                *(__half2*)(Psw + rr * 64 + c0 + c) = __floats2half2_rn(p0, p1);
            }
            sum += __shfl_xor_sync(0xffffffffu, sum, 1);
            sum += __shfl_xor_sync(0xffffffffu, sum, 2);
            m_st = m_new;
            l_st = l_st * factor + sum;
#pragma unroll
            for (int c = 0; c < 16; c++) Oreg[c] *= factor;
        }
        __syncwarp();

        // Onew = P(8x64) @ V(64x64) -> Ssw
        {
            wmma::fragment<wmma::matrix_a, 8, 32, 16, __half, wmma::row_major> af[4];
#pragma unroll
            for (int kk = 0; kk < 4; kk++)
                wmma::load_matrix_sync(af[kk], Psw + kk * 16, 64);
#pragma unroll
            for (int n = 0; n < 2; n++) {
                wmma::fragment<wmma::accumulator, 8, 32, 16, float> cfr;
                wmma::fill_fragment(cfr, 0.0f);
#pragma unroll
                for (int kk = 0; kk < 4; kk++) {
                    wmma::fragment<wmma::matrix_b, 8, 32, 16, __half, wmma::row_major> bf;
                    wmma::load_matrix_sync(bf, vd + (kk * 16) * 72 + n * 32, 72);
                    wmma::mma_sync(cfr, af[kk], bf, cfr);
                }
                wmma::store_matrix_sync(Ssw + n * 32, cfr, 72, wmma::mem_row_major);
            }
        }
        __syncwarp();
#pragma unroll
        for (int c = 0; c < 16; c++) Oreg[c] += Ssw[rr * 72 + c0 + c];
        __syncwarp();

        __syncthreads();
    }

    {
        float inv = 1.0f / l_st;
        size_t gb = (size_t)(b * Lc + i_abs) * Dc + h * 64 + c0;
#pragma unroll
        for (int c = 0; c < 16; c += 2)
            *(__half2*)(o + gb + c) = __floats2half2_rn(Oreg[c] * inv, Oreg[c + 1] * inv);
    }
}

// ================= mega-prologue (single launch) =================
#define PROL_BLOCKS 26848
__global__ __launch_bounds__(256) void prol_k(
    const float* __restrict__ Wq, const float* __restrict__ Wk, const float* __restrict__ Wv,
    const float* __restrict__ Wo, const float* __restrict__ W1, const float* __restrict__ W2,
    __half* __restrict__ wqkv, __half* __restrict__ wo,
    __half* __restrict__ w1, __half* __restrict__ w2,
    const float* __restrict__ src, float* __restrict__ x, __half* __restrict__ xh,
    const float* __restrict__ bq, const float* __restrict__ bk, const float* __restrict__ bv,
    float* __restrict__ bqkv, float* __restrict__ pe)
{
    __shared__ float t[64][65];
    const int bid = blockIdx.x, tid = threadIdx.x;

    const float* in; __half* out; int N, K, n0, k0;
    if (bid < 6144) {
        int z = bid >> 8, rem = bid & 255;
        int sel = z / NLc, l = z - sel * NLc;
        in  = ((sel == 0) ? Wq : (sel == 1) ? Wk : Wv) + (size_t)l * Dc * Dc;
        out = wqkv + (size_t)l * 3 * Dc * Dc + (size_t)sel * Dc * Dc;
        N = Dc; K = Dc; n0 = (rem >> 4) * 64; k0 = (rem & 15) * 64;
    } else if (bid < 8192) {
        int rem = bid - 6144; int l = rem >> 8; int r2 = rem & 255;
        in = Wo + (size_t)l * Dc * Dc; out = wo + (size_t)l * Dc * Dc;
        N = Dc; K = Dc; n0 = (r2 >> 4) * 64; k0 = (r2 & 15) * 64;
    } else if (bid < 16384) {
        int rem = bid - 8192; int l = rem >> 10; int r2 = rem & 1023;
        in = W1 + (size_t)l * Dc * FFc; out = w1 + (size_t)l * Dc * FFc;
        N = FFc; K = Dc; n0 = (r2 >> 4) * 64; k0 = (r2 & 15) * 64;
    } else if (bid < 24576) {
        int rem = bid - 16384; int l = rem >> 10; int r2 = rem & 1023;
        in = W2 + (size_t)l * Dc * FFc; out = w2 + (size_t)l * Dc * FFc;
        N = Dc; K = FFc; n0 = (r2 >> 6) * 64; k0 = (r2 & 63) * 64;
    } else {
        int pb = bid - 24576;
        if (pb < 2048) {
            int i = pb * 256 + tid;
            float4 v = ((const float4*)src)[i];
            ((float4*)x)[i] = v;
            ((__half2*)xh)[2 * i]     = __floats2half2_rn(v.x, v.y);
            ((__half2*)xh)[2 * i + 1] = __floats2half2_rn(v.z, v.w);
        } else if (pb < 2176) {
            int idx = (pb - 2048) * 256 + tid;
            int pos = idx >> 5, f = idx & 31;
            float inv = powf(10000.0f, -(float)f * (1.0f / 32.0f));
            float ang = (float)pos * inv;
            pe[pos * 64 + f]      = cosf(ang);
            pe[pos * 64 + 32 + f] = sinf(ang);
        } else {
            int i = (pb - 2176) * 256 + tid;
            int l = i / (3 * Dc), c = i % (3 * Dc);
            float v = (c < Dc) ? bq[l * Dc + c] : (c < 2 * Dc) ? bk[l * Dc + c - Dc] : bv[l * Dc + c - 2 * Dc];
            bqkv[i] = v;
        }
        return;
    }

    const int tx = tid & 31, ty = tid >> 5;
#pragma unroll
    for (int i = 0; i < 8; i++) {
        int r = ty + i * 8;
        const float* rp = in + (size_t)(k0 + r) * N + n0;
        t[r][tx]      = rp[tx];
        t[r][tx + 32] = rp[tx + 32];
    }
    __syncthreads();
#pragma unroll
    for (int i = 0; i < 8; i++) {
        int nr = ty + i * 8;
        *(__half2*)(out + (size_t)(n0 + nr) * K + k0 + 2 * tx) =
            __floats2half2_rn(t[2 * tx][nr], t[2 * tx + 1][nr]);
    }
}

// ---------------- LayerNorm over (t0 + t1 + res + bias): warp-per-row ----------------
__global__ __launch_bounds__(256) void lnr_k(
    const float* __restrict__ t0, const float* __restrict__ t1,
    const float* __restrict__ res, const float* __restrict__ bias,
    const float* __restrict__ g, const float* __restrict__ bt,
    float* __restrict__ out, __half* __restrict__ outh)
{
    const int row  = blockIdx.x * 8 + (threadIdx.x >> 5);
    const int lane = threadIdx.x & 31;
    const float4* p0 = (const float4*)(t0  + (size_t)row * Dc);
    const float4* p1 = (const float4*)(t1  + (size_t)row * Dc);
    const float4* pr = (const float4*)(res + (size_t)row * Dc);
    const float4* pb = (const float4*)bias;

    float4 v[8];
    float sum = 0.0f;
#pragma unroll
    for (int i = 0; i < 8; i++) {
        float4 a = p0[lane + i * 32], b = p1[lane + i * 32];
        float4 r = pr[lane + i * 32], bi = pb[lane + i * 32];
        v[i].x = a.x + b.x + r.x + bi.x;
        v[i].y = a.y + b.y + r.y + bi.y;
        v[i].z = a.z + b.z + r.z + bi.z;
        v[i].w = a.w + b.w + r.w + bi.w;
        sum += v[i].x + v[i].y + v[i].z + v[i].w;
    }
#pragma unroll
    for (int o = 16; o; o >>= 1) sum += __shfl_xor_sync(0xffffffffu, sum, o);
    const float mu = sum * (1.0f / Dc);

    float var = 0.0f;
#pragma unroll
    for (int i = 0; i < 8; i++) {
        v[i].x -= mu; v[i].y -= mu; v[i].z -= mu; v[i].w -= mu;
        var += v[i].x * v[i].x + v[i].y * v[i].y + v[i].z * v[i].z + v[i].w * v[i].w;
    }
#pragma unroll
    for (int o = 16; o; o >>= 1) var += __shfl_xor_sync(0xffffffffu, var, o);
    const float inv = rsqrtf(var * (1.0f / Dc) + 1e-5f);

    float4* po = (float4*)(out + (size_t)row * Dc);
    __half2* ph = (__half2*)(outh + (size_t)row * Dc);
#pragma unroll
    for (int i = 0; i < 8; i++) {
        float4 gg = ((const float4*)g)[lane + i * 32];
        float4 bb = ((const float4*)bt)[lane + i * 32];
        float4 r;
        r.x = v[i].x * inv * gg.x + bb.x;
        r.y = v[i].y * inv * gg.y + bb.y;
        r.z = v[i].z * inv * gg.z + bb.z;
        r.w = v[i].w * inv * gg.w + bb.w;
        po[lane + i * 32] = r;
        ph[(lane + i * 32) * 2]     = __floats2half2_rn(r.x, r.y);
        ph[(lane + i * 32) * 2 + 1] = __floats2half2_rn(r.z, r.w);
    }
}

// ---------------- final LayerNorm ----------------
__global__ __launch_bounds__(256) void ln_k(
    const float* __restrict__ in, const float* __restrict__ g,
    const float* __restrict__ bt, float* __restrict__ out)
{
    const int row  = blockIdx.x * 8 + (threadIdx.x >> 5);
    const int lane = threadIdx.x & 31;
    const float4* p = (const float4*)(in + (size_t)row * Dc);

    float4 v[8];
    float sum = 0.0f;
#pragma unroll
    for (int i = 0; i < 8; i++) {
        v[i] = p[lane + i * 32];
        sum += v[i].x + v[i].y + v[i].z + v[i].w;
    }
#pragma unroll
    for (int o = 16; o; o >>= 1) sum += __shfl_xor_sync(0xffffffffu, sum, o);
    const float mu = sum * (1.0f / Dc);

    float var = 0.0f;
#pragma unroll
    for (int i = 0; i < 8; i++) {
        v[i].x -= mu; v[i].y -= mu; v[i].z -= mu; v[i].w -= mu;
        var += v[i].x * v[i].x + v[i].y * v[i].y + v[i].z * v[i].z + v[i].w * v[i].w;
    }
#pragma unroll
    for (int o = 16; o; o >>= 1) var += __shfl_xor_sync(0xffffffffu, var, o);
    const float inv = rsqrtf(var * (1.0f / Dc) + 1e-5f);

    float4* po = (float4*)(out + (size_t)row * Dc);
#pragma unroll
    for (int i = 0; i < 8; i++) {
        float4 gg = ((const float4*)g)[lane + i * 32];
        float4 bb = ((const float4*)bt)[lane + i * 32];
        float4 r;
        r.x = v[i].x * inv * gg.x + bb.x;
        r.y = v[i].y * inv * gg.y + bb.y;
        r.z = v[i].z * inv * gg.z + bb.z;
        r.w = v[i].w * inv * gg.w + bb.w;
        po[lane + i * 32] = r;
    }
}

// ---------------- host orchestration ----------------
extern "C" void kernel_launch(void* const* d_in, const int* in_sizes, int n_in,
                              void* d_out, int out_size)
{
    const float* src = (const float*)d_in[0];
    const float* Wq  = (const float*)d_in[1];
    const float* bq  = (const float*)d_in[2];
    const float* Wk  = (const float*)d_in[3];
    const float* bk  = (const float*)d_in[4];
    const float* Wv  = (const float*)d_in[5];
    const float* bv  = (const float*)d_in[6];
    const float* Wo  = (const float*)d_in[7];
    const float* bo  = (const float*)d_in[8];
    const float* W1  = (const float*)d_in[9];
    const float* b1  = (const float*)d_in[10];
    const float* W2  = (const float*)d_in[11];
    const float* b2  = (const float*)d_in[12];
    const float* g1  = (const float*)d_in[13];
    const float* be1 = (const float*)d_in[14];
    const float* g2  = (const float*)d_in[15];
    const float* be2 = (const float*)d_in[16];
    const float* gf  = (const float*)d_in[17];
    const float* bf  = (const float*)d_in[18];

    float *x, *tmp, *tmp2, *pe, *bqkv;
    __half *xh, *qh, *kh, *vh, *oh, *ffh, *wqkvh, *woh, *w1h, *w2h;
    cudaGetSymbolAddress((void**)&x,    g_x);
    cudaGetSymbolAddress((void**)&tmp,  g_tmp);
    cudaGetSymbolAddress((void**)&tmp2, g_tmp2);
    cudaGetSymbolAddress((void**)&pe,   g_pe);
    cudaGetSymbolAddress((void**)&bqkv, g_bqkv);
    cudaGetSymbolAddress((void**)&xh,   g_xh);
    cudaGetSymbolAddress((void**)&qh,   g_qh);
    cudaGetSymbolAddress((void**)&kh,   g_kh);
    cudaGetSymbolAddress((void**)&vh,   g_vh);
    cudaGetSymbolAddress((void**)&oh,   g_oh);
    cudaGetSymbolAddress((void**)&ffh,  g_ffh);
    cudaGetSymbolAddress((void**)&wqkvh,g_wqkv);
    cudaGetSymbolAddress((void**)&woh,  g_wo);
    cudaGetSymbolAddress((void**)&w1h,  g_w1);
    cudaGetSymbolAddress((void**)&w2h,  g_w2);

    cudaFuncSetAttribute(gemm_qkv, cudaFuncAttributeMaxDynamicSharedMemorySize, GEMM_DSM);
    cudaFuncSetAttribute(gemm_g,   cudaFuncAttributeMaxDynamicSharedMemorySize, GEMM_DSM);
    cudaFuncSetAttribute(gemm_s,   cudaFuncAttributeMaxDynamicSharedMemorySize, GEMM_DSM);
    cudaFuncSetAttribute(fa_k,     cudaFuncAttributeMaxDynamicSharedMemorySize, FA_DSM);

    prol_k<<<PROL_BLOCKS, 256>>>(Wq, Wk, Wv, Wo, W1, W2,
                                 wqkvh, woh, w1h, w2h,
                                 src, x, xh, bq, bk, bv, bqkv, pe);

    const int M = Mtot;
    const size_t DD = (size_t)Dc * Dc;
    dim3 gQKV(3 * Dc / 128, M / 128);      // (24, 16)
    dim3 gF(FFc / 128, M / 128);           // (32, 16)
    dim3 gS(Dc / 128, M / 128, 2);         // (8, 16, 2) split-K
    dim3 gFA(Lc / 64, Bc * Hc);            // (16, 32) = 512 blocks
    const int gLN = M / 8;                 // 256 blocks

    for (int l = 0; l < NLc; l++) {
        const __half* wqkvl = wqkvh + (size_t)l * 3 * DD;
        const __half* wo = woh + (size_t)l * DD;
        const __half* w1 = w1h + (size_t)l * Dc * FFc;
        const __half* w2 = w2h + (size_t)l * FFc * Dc;

        gemm_qkv<<<gQKV, 256, GEMM_DSM>>>(xh, wqkvl, bqkv + l * 3 * Dc, pe, qh, kh, vh, M, 3 * Dc, Dc);
        fa_k<<<gFA, 256, FA_DSM>>>(qh, kh, vh, oh);

        gemm_s<<<gS, 256, GEMM_DSM>>>(oh, wo, tmp, tmp2, Dc, Dc / 2, Dc);
        lnr_k<<<gLN, 256>>>(tmp, tmp2, x, bo + l * Dc, g1 + l * Dc, be1 + l * Dc, x, xh);

        gemm_g<<<gF, 256, GEMM_DSM>>>(xh, w1, b1 + (size_t)l * FFc, ffh, M, FFc, Dc);
        gemm_s<<<gS, 256, GEMM_DSM>>>(ffh, w2, tmp, tmp2, Dc, FFc / 2, FFc);
        lnr_k<<<gLN, 256>>>(tmp, tmp2, x, b2 + l * Dc, g2 + l * Dc, be2 + l * Dc, x, xh);
    }

    ln_k<<<gLN, 256>>>(x, gf, bf, (float*)d_out);
}

// round 17
// speedup vs baseline: 1.0761x; 1.0761x over previous
#include <cuda_runtime.h>
#include <cuda_fp16.h>
#include <mma.h>
#include <math.h>
#include <stdint.h>

using namespace nvcuda;

#define Bc 2
#define Lc 1024
#define Dc 1024
#define Hc 16
#define HDc 64
#define FFc 4096
#define NLc 8
#define Mtot (Bc*Lc)

// ---------------- scratch (device globals; no allocation) ----------------
__device__ float g_x   [Mtot*Dc];
__device__ float g_tmp [Mtot*Dc];
__device__ float g_tmp2[Mtot*Dc];
__device__ float g_pe  [Lc*HDc];
__device__ float g_bqkv[NLc*3*Dc];

__device__ __half g_xh [Mtot*Dc];
__device__ __half g_qh [Mtot*Dc];
__device__ __half g_kh [Mtot*Dc];
__device__ __half g_vh [Mtot*Dc];
__device__ __half g_oh [Mtot*Dc];
__device__ __half g_ffh[(size_t)Mtot*FFc];
__device__ __half g_wqkv[(size_t)NLc*3*Dc*Dc];
__device__ __half g_wo [(size_t)NLc*Dc*Dc];
__device__ __half g_w1 [(size_t)NLc*Dc*FFc];
__device__ __half g_w2 [(size_t)NLc*FFc*Dc];

__device__ __forceinline__ float gelu_exact(float x) {
    return 0.5f * x * (1.0f + erff(x * 0.70710678118654752f));
}
__device__ __forceinline__ void cp_async16(uint32_t saddr, const void* gaddr) {
    asm volatile("cp.async.cg.shared.global [%0], [%1], 16;" :: "r"(saddr), "l"(gaddr));
}
__device__ __forceinline__ uint32_t smem_u32(const void* p) {
    uint32_t a;
    asm("{ .reg .u64 t; cvta.to.shared.u64 t, %1; cvt.u32.u64 %0, t; }" : "=r"(a) : "l"(p));
    return a;
}

// ================= 128x128 wmma GEMM core (8 warps, 64x32, BK64, 2-stage) =================
#define BKc 64
#define LDS 72
#define GEMM_DSM (4*128*LDS*2)   // 73728 B; C tile (67584) aliases where staged

#define GEMM_MAINLOOP_CORE(Ap, Bp, Kc, ld)                                                         \
    __half (*As)[128][LDS] = (__half (*)[128][LDS])dsm;                                            \
    __half (*Bs)[128][LDS] = (__half (*)[128][LDS])(dsm + 2 * 128 * LDS * 2);                      \
    const int tid = threadIdx.x;                                                                   \
    const int w = tid >> 5;                                                                        \
    const int wm = w & 1;                                                                          \
    const int wn = w >> 1;                                                                         \
    const int row0 = blockIdx.y * 128, col0 = blockIdx.x * 128;                                    \
    wmma::fragment<wmma::accumulator, 16, 16, 16, float> acc[4][2];                                \
    _Pragma("unroll")                                                                              \
    for (int i = 0; i < 4; i++)                                                                    \
        _Pragma("unroll")                                                                          \
        for (int j = 0; j < 2; j++) wmma::fill_fragment(acc[i][j], 0.0f);                          \
    const int nch = (Kc) / BKc;                                                                    \
    auto issue_chunk = [&](int buf, int c0) {                                                      \
        _Pragma("unroll")                                                                          \
        for (int i = 0; i < 4; i++) {                                                              \
            int s = tid + i * 256;                                                                 \
            int r = s >> 3, cc = (s & 7) * 8;                                                      \
            cp_async16(smem_u32(&As[buf][r][cc]), (Ap) + (size_t)(row0 + r) * (ld) + c0 + cc);     \
            cp_async16(smem_u32(&Bs[buf][r][cc]), (Bp) + (size_t)(col0 + r) * (ld) + c0 + cc);     \
        }                                                                                          \
        asm volatile("cp.async.commit_group;" ::: "memory");                                       \
    };                                                                                             \
    issue_chunk(0, 0);                                                                             \
    for (int c = 0; c < nch; c++) {                                                                \
        const int buf = c & 1;                                                                     \
        if (c + 1 < nch) {                                                                         \
            issue_chunk(buf ^ 1, (c + 1) * BKc);                                                   \
            asm volatile("cp.async.wait_group 1;" ::: "memory");                                   \
        } else {                                                                                   \
            asm volatile("cp.async.wait_group 0;" ::: "memory");                                   \
        }                                                                                          \
        __syncthreads();                                                                           \
        _Pragma("unroll")                                                                          \
        for (int kk = 0; kk < 4; kk++) {                                                           \
            wmma::fragment<wmma::matrix_a, 16, 16, 16, __half, wmma::row_major> af[4];             \
            wmma::fragment<wmma::matrix_b, 16, 16, 16, __half, wmma::col_major> bf[2];             \
            _Pragma("unroll")                                                                      \
            for (int i = 0; i < 4; i++)                                                            \
                wmma::load_matrix_sync(af[i], &As[buf][wm * 64 + i * 16][kk * 16], LDS);           \
            _Pragma("unroll")                                                                      \
            for (int j = 0; j < 2; j++)                                                            \
                wmma::load_matrix_sync(bf[j], &Bs[buf][wn * 32 + j * 16][kk * 16], LDS);           \
            _Pragma("unroll")                                                                      \
            for (int i = 0; i < 4; i++)                                                            \
                _Pragma("unroll")                                                                  \
                for (int j = 0; j < 2; j++)                                                        \
                    wmma::mma_sync(acc[i][j], af[i], bf[j], acc[i][j]);                            \
        }                                                                                          \
        __syncthreads();                                                                           \
    }

#define GEMM_STAGE_C()                                                                             \
    float* Cs = (float*)dsm;                                                                       \
    _Pragma("unroll")                                                                              \
    for (int i = 0; i < 4; i++)                                                                    \
        _Pragma("unroll")                                                                          \
        for (int j = 0; j < 2; j++)                                                                \
            wmma::store_matrix_sync(Cs + (size_t)(wm * 64 + i * 16) * 132 + wn * 32 + j * 16,      \
                                    acc[i][j], 132, wmma::mem_row_major);                          \
    __syncthreads();

// ---- FF1 GEMM: f16 gelu(+bias) ----
__global__ __launch_bounds__(256) void gemm_g(
    const __half* __restrict__ A, const __half* __restrict__ Bt,
    const float* __restrict__ bias, __half* __restrict__ Ch, int M, int N, int K)
{
    extern __shared__ char dsm[];
    GEMM_MAINLOOP_CORE(A, Bt, K, K)
    GEMM_STAGE_C()

#pragma unroll
    for (int it = 0; it < 16; it++) {
        int vlin = tid + it * 256;
        int row = vlin >> 5;
        int vc = (vlin & 31) * 4;
        float4 v = *(float4*)(Cs + (size_t)row * 132 + vc);
        float4 b = *(const float4*)(bias + col0 + vc);
        v.x = gelu_exact(v.x + b.x); v.y = gelu_exact(v.y + b.y);
        v.z = gelu_exact(v.z + b.z); v.w = gelu_exact(v.w + b.w);
        size_t gidx = (size_t)(row0 + row) * N + col0 + vc;
        *(__half2*)(Ch + gidx)     = __floats2half2_rn(v.x, v.y);
        *(__half2*)(Ch + gidx + 2) = __floats2half2_rn(v.z, v.w);
    }
}

// ---- split-K GEMM (z in {0,1}): direct fragment store to fp32 partial buffer ----
__global__ __launch_bounds__(256) void gemm_s(
    const __half* __restrict__ A, const __half* __restrict__ Bt,
    float* __restrict__ Cf0, float* __restrict__ Cf1, int N, int Kh, int ld)
{
    extern __shared__ char dsm[];
    const int z = blockIdx.z;
    const __half* Ap = A  + z * Kh;
    const __half* Bp = Bt + z * Kh;
    GEMM_MAINLOOP_CORE(Ap, Bp, Kh, ld)

    float* Cf = z ? Cf1 : Cf0;
#pragma unroll
    for (int i = 0; i < 4; i++)
#pragma unroll
        for (int j = 0; j < 2; j++)
            wmma::store_matrix_sync(
                Cf + (size_t)(row0 + wm * 64 + i * 16) * N + col0 + wn * 32 + j * 16,
                acc[i][j], N, wmma::mem_row_major);
}

// ---- QKV GEMM with fused bias + RoPE + fp16 convert epilogue ----
__global__ __launch_bounds__(256) void gemm_qkv(
    const __half* __restrict__ A, const __half* __restrict__ Bt,
    const float* __restrict__ bias, const float* __restrict__ pe,
    __half* __restrict__ qh, __half* __restrict__ kh, __half* __restrict__ vh,
    int M, int N, int K)
{
    extern __shared__ char dsm[];
    GEMM_MAINLOOP_CORE(A, Bt, K, K)
    GEMM_STAGE_C()

#pragma unroll
    for (int it = 0; it < 16; it++) {
        int vlin = tid + it * 256;
        int row = vlin >> 5;
        int vc = (vlin & 31) * 4;
        float4 v = *(float4*)(Cs + (size_t)row * 132 + vc);
        float4 b = *(const float4*)(bias + col0 + vc);
        v.x += b.x; v.y += b.y; v.z += b.z; v.w += b.w;

        const int grow = row0 + row;
        const int gcol = col0 + vc;
        if (gcol < 2 * Dc) {
            const int l = grow & (Lc - 1);
            const int d = gcol & 63;
            const int head = (gcol & 1023) >> 6;
            const int j = d >> 1;
            float4 p4 = *(const float4*)(pe + l * 64 + d);
            float e1 = v.x * p4.x - v.y * p4.y;
            float o1 = v.x * p4.y + v.y * p4.x;
            float e2 = v.z * p4.z - v.w * p4.w;
            float o2 = v.z * p4.w + v.w * p4.z;
            __half* dst;
            if (gcol < Dc) {
                e1 *= 0.125f; o1 *= 0.125f; e2 *= 0.125f; o2 *= 0.125f;
                dst = qh;
            } else {
                dst = kh;
            }
            size_t base = (size_t)grow * Dc + head * 64;
            *(__half2*)(dst + base + j)      = __floats2half2_rn(e1, e2);
            *(__half2*)(dst + base + 32 + j) = __floats2half2_rn(o1, o2);
        } else {
            size_t gidx = (size_t)grow * Dc + (gcol - 2 * Dc);
            *(__half2*)(vh + gidx)     = __floats2half2_rn(v.x, v.y);
            *(__half2*)(vh + gidx + 2) = __floats2half2_rn(v.z, v.w);
        }
    }
}

// ================= flash attention v2 (proven config: 128-row Q tile, 16x16 frags) =================
#define FA_Q   0
#define FA_K   18432
#define FA_V   36864
#define FA_S   55296
#define FA_P   92160
#define FA_DSM 108544
__global__ __launch_bounds__(256) void fa_k(
    const __half* __restrict__ q, const __half* __restrict__ k,
    const __half* __restrict__ v, __half* __restrict__ o)
{
    extern __shared__ char dsm[];
    __half* Qs = (__half*)(dsm + FA_Q);
    __half* Kb = (__half*)(dsm + FA_K);
    __half* Vb = (__half*)(dsm + FA_V);

    const int tid = threadIdx.x;
    const int w = tid >> 5, lane = tid & 31;
    const int bh = blockIdx.y;
    const int b = bh >> 4, h = bh & 15;
    const int i0 = blockIdx.x * 128;
    const float slope = exp2f(-0.5f * (float)h);

    float* Ssw = (float*)(dsm + FA_S) + w * 16 * 72;
    __half* Psw = (__half*)(dsm + FA_P) + w * 16 * 64;

#pragma unroll
    for (int i = 0; i < 4; i++) {
        int s = tid + i * 256;
        int r = s >> 3, u = (s & 7) * 8;
        *(uint4*)(Qs + r * 72 + u) = *(const uint4*)(q + (size_t)(b * Lc + i0 + r) * Dc + h * 64 + u);
    }

    auto issue_kv = [&](int buf, int j0) {
        __half* kd = Kb + buf * 64 * 72;
        __half* vd = Vb + buf * 64 * 72;
#pragma unroll
        for (int i = 0; i < 2; i++) {
            int s = tid + i * 256;
            int r = s >> 3, u = (s & 7) * 8;
            cp_async16(smem_u32(kd + r * 72 + u), k + (size_t)(b * Lc + j0 + r) * Dc + h * 64 + u);
            cp_async16(smem_u32(vd + r * 72 + u), v + (size_t)(b * Lc + j0 + r) * Dc + h * 64 + u);
        }
        asm volatile("cp.async.commit_group;" ::: "memory");
    };

    const int rr = lane >> 1;
    const int c0 = (lane & 1) * 32;
    const int i_abs = i0 + w * 16 + rr;

    float Oreg[32];
#pragma unroll
    for (int c = 0; c < 32; c++) Oreg[c] = 0.0f;
    float m_st = -1e30f, l_st = 0.0f;

    issue_kv(0, 0);
    __syncthreads();

    for (int jt = 0; jt < Lc / 64; jt++) {
        const int buf = jt & 1;
        const int j0 = jt * 64;
        if (jt + 1 < Lc / 64) {
            issue_kv(buf ^ 1, j0 + 64);
            asm volatile("cp.async.wait_group 1;" ::: "memory");
        } else {
            asm volatile("cp.async.wait_group 0;" ::: "memory");
        }
        __syncthreads();

        const __half* kd = Kb + buf * 64 * 72;
        const __half* vd = Vb + buf * 64 * 72;

        {
            wmma::fragment<wmma::matrix_a, 16, 16, 16, __half, wmma::row_major> af[4];
#pragma unroll
            for (int kk = 0; kk < 4; kk++)
                wmma::load_matrix_sync(af[kk], Qs + (w * 16) * 72 + kk * 16, 72);
#pragma unroll
            for (int n = 0; n < 4; n++) {
                wmma::fragment<wmma::accumulator, 16, 16, 16, float> cfr;
                wmma::fill_fragment(cfr, 0.0f);
#pragma unroll
                for (int kk = 0; kk < 4; kk++) {
                    wmma::fragment<wmma::matrix_b, 16, 16, 16, __half, wmma::col_major> bf;
                    wmma::load_matrix_sync(bf, kd + (n * 16) * 72 + kk * 16, 72);
                    wmma::mma_sync(cfr, af[kk], bf, cfr);
                }
                wmma::store_matrix_sync(Ssw + n * 16, cfr, 72, wmma::mem_row_major);
            }
        }
        __syncwarp();

        {
            float s[32];
            float mx = -1e30f;
#pragma unroll
            for (int c = 0; c < 32; c++) {
                int j_abs = j0 + c0 + c;
                float bias = (i_abs > j_abs) ? slope * (float)(i_abs - j_abs) : 0.0f;
                s[c] = Ssw[rr * 72 + c0 + c] + bias;
                mx = fmaxf(mx, s[c]);
            }
            mx = fmaxf(mx, __shfl_xor_sync(0xffffffffu, mx, 1));
            float m_new = fmaxf(m_st, mx);
            float factor = __expf(m_st - m_new);
            float sum = 0.0f;
#pragma unroll
            for (int c = 0; c < 32; c += 2) {
                float p0 = __expf(s[c] - m_new);
                float p1 = __expf(s[c + 1] - m_new);
                sum += p0 + p1;
                *(__half2*)(Psw + rr * 64 + c0 + c) = __floats2half2_rn(p0, p1);
            }
            sum += __shfl_xor_sync(0xffffffffu, sum, 1);
            m_st = m_new;
            l_st = l_st * factor + sum;
#pragma unroll
            for (int c = 0; c < 32; c++) Oreg[c] *= factor;
        }
        __syncwarp();

        {
            wmma::fragment<wmma::matrix_a, 16, 16, 16, __half, wmma::row_major> af[4];
#pragma unroll
            for (int kk = 0; kk < 4; kk++)
                wmma::load_matrix_sync(af[kk], Psw + kk * 16, 64);
#pragma unroll
            for (int n = 0; n < 4; n++) {
                wmma::fragment<wmma::accumulator, 16, 16, 16, float> cfr;
                wmma::fill_fragment(cfr, 0.0f);
#pragma unroll
                for (int kk = 0; kk < 4; kk++) {
                    wmma::fragment<wmma::matrix_b, 16, 16, 16, __half, wmma::row_major> bf;
                    wmma::load_matrix_sync(bf, vd + (kk * 16) * 72 + n * 16, 72);
                    wmma::mma_sync(cfr, af[kk], bf, cfr);
                }
                wmma::store_matrix_sync(Ssw + n * 16, cfr, 72, wmma::mem_row_major);
            }
        }
        __syncwarp();
#pragma unroll
        for (int c = 0; c < 32; c++) Oreg[c] += Ssw[rr * 72 + c0 + c];
        __syncwarp();

        __syncthreads();
    }

    {
        float inv = 1.0f / l_st;
        size_t gb = (size_t)(b * Lc + i_abs) * Dc + h * 64 + c0;
#pragma unroll
        for (int c = 0; c < 32; c += 2)
            *(__half2*)(o + gb + c) = __floats2half2_rn(Oreg[c] * inv, Oreg[c + 1] * inv);
    }
}

// ================= mega-prologue (single launch) =================
#define PROL_BLOCKS 26848
__global__ __launch_bounds__(256) void prol_k(
    const float* __restrict__ Wq, const float* __restrict__ Wk, const float* __restrict__ Wv,
    const float* __restrict__ Wo, const float* __restrict__ W1, const float* __restrict__ W2,
    __half* __restrict__ wqkv, __half* __restrict__ wo,
    __half* __restrict__ w1, __half* __restrict__ w2,
    const float* __restrict__ src, float* __restrict__ x, __half* __restrict__ xh,
    const float* __restrict__ bq, const float* __restrict__ bk, const float* __restrict__ bv,
    float* __restrict__ bqkv, float* __restrict__ pe)
{
    __shared__ float t[64][65];
    const int bid = blockIdx.x, tid = threadIdx.x;

    const float* in; __half* out; int N, K, n0, k0;
    if (bid < 6144) {
        int z = bid >> 8, rem = bid & 255;
        int sel = z / NLc, l = z - sel * NLc;
        in  = ((sel == 0) ? Wq : (sel == 1) ? Wk : Wv) + (size_t)l * Dc * Dc;
        out = wqkv + (size_t)l * 3 * Dc * Dc + (size_t)sel * Dc * Dc;
        N = Dc; K = Dc; n0 = (rem >> 4) * 64; k0 = (rem & 15) * 64;
    } else if (bid < 8192) {
        int rem = bid - 6144; int l = rem >> 8; int r2 = rem & 255;
        in = Wo + (size_t)l * Dc * Dc; out = wo + (size_t)l * Dc * Dc;
        N = Dc; K = Dc; n0 = (r2 >> 4) * 64; k0 = (r2 & 15) * 64;
    } else if (bid < 16384) {
        int rem = bid - 8192; int l = rem >> 10; int r2 = rem & 1023;
        in = W1 + (size_t)l * Dc * FFc; out = w1 + (size_t)l * Dc * FFc;
        N = FFc; K = Dc; n0 = (r2 >> 4) * 64; k0 = (r2 & 15) * 64;
    } else if (bid < 24576) {
        int rem = bid - 16384; int l = rem >> 10; int r2 = rem & 1023;
        in = W2 + (size_t)l * Dc * FFc; out = w2 + (size_t)l * Dc * FFc;
        N = Dc; K = FFc; n0 = (r2 >> 6) * 64; k0 = (r2 & 63) * 64;
    } else {
        int pb = bid - 24576;
        if (pb < 2048) {
            int i = pb * 256 + tid;
            float4 v = ((const float4*)src)[i];
            ((float4*)x)[i] = v;
            ((__half2*)xh)[2 * i]     = __floats2half2_rn(v.x, v.y);
            ((__half2*)xh)[2 * i + 1] = __floats2half2_rn(v.z, v.w);
        } else if (pb < 2176) {
            int idx = (pb - 2048) * 256 + tid;
            int pos = idx >> 5, f = idx & 31;
            float inv = powf(10000.0f, -(float)f * (1.0f / 32.0f));
            float ang = (float)pos * inv;
            pe[pos * 64 + f]      = cosf(ang);
            pe[pos * 64 + 32 + f] = sinf(ang);
        } else {
            int i = (pb - 2176) * 256 + tid;
            int l = i / (3 * Dc), c = i % (3 * Dc);
            float v = (c < Dc) ? bq[l * Dc + c] : (c < 2 * Dc) ? bk[l * Dc + c - Dc] : bv[l * Dc + c - 2 * Dc];
            bqkv[i] = v;
        }
        return;
    }

    const int tx = tid & 31, ty = tid >> 5;
#pragma unroll
    for (int i = 0; i < 8; i++) {
        int r = ty + i * 8;
        const float* rp = in + (size_t)(k0 + r) * N + n0;
        t[r][tx]      = rp[tx];
        t[r][tx + 32] = rp[tx + 32];
    }
    __syncthreads();
#pragma unroll
    for (int i = 0; i < 8; i++) {
        int nr = ty + i * 8;
        *(__half2*)(out + (size_t)(n0 + nr) * K + k0 + 2 * tx) =
            __floats2half2_rn(t[2 * tx][nr], t[2 * tx + 1][nr]);
    }
}

// ---------------- LayerNorm over (t0 + t1 + res + bias): warp-per-row ----------------
__global__ __launch_bounds__(256) void lnr_k(
    const float* __restrict__ t0, const float* __restrict__ t1,
    const float* __restrict__ res, const float* __restrict__ bias,
    const float* __restrict__ g, const float* __restrict__ bt,
    float* __restrict__ out, __half* __restrict__ outh)
{
    const int row  = blockIdx.x * 8 + (threadIdx.x >> 5);
    const int lane = threadIdx.x & 31;
    const float4* p0 = (const float4*)(t0  + (size_t)row * Dc);
    const float4* p1 = (const float4*)(t1  + (size_t)row * Dc);
    const float4* pr = (const float4*)(res + (size_t)row * Dc);
    const float4* pb = (const float4*)bias;

    float4 v[8];
    float sum = 0.0f;
#pragma unroll
    for (int i = 0; i < 8; i++) {
        float4 a = p0[lane + i * 32], b = p1[lane + i * 32];
        float4 r = pr[lane + i * 32], bi = pb[lane + i * 32];
        v[i].x = a.x + b.x + r.x + bi.x;
        v[i].y = a.y + b.y + r.y + bi.y;
        v[i].z = a.z + b.z + r.z + bi.z;
        v[i].w = a.w + b.w + r.w + bi.w;
        sum += v[i].x + v[i].y + v[i].z + v[i].w;
    }
#pragma unroll
    for (int o = 16; o; o >>= 1) sum += __shfl_xor_sync(0xffffffffu, sum, o);
    const float mu = sum * (1.0f / Dc);

    float var = 0.0f;
#pragma unroll
    for (int i = 0; i < 8; i++) {
        v[i].x -= mu; v[i].y -= mu; v[i].z -= mu; v[i].w -= mu;
        var += v[i].x * v[i].x + v[i].y * v[i].y + v[i].z * v[i].z + v[i].w * v[i].w;
    }
#pragma unroll
    for (int o = 16; o; o >>= 1) var += __shfl_xor_sync(0xffffffffu, var, o);
    const float inv = rsqrtf(var * (1.0f / Dc) + 1e-5f);

    float4* po = (float4*)(out + (size_t)row * Dc);
    __half2* ph = (__half2*)(outh + (size_t)row * Dc);
#pragma unroll
    for (int i = 0; i < 8; i++) {
        float4 gg = ((const float4*)g)[lane + i * 32];
        float4 bb = ((const float4*)bt)[lane + i * 32];
        float4 r;
        r.x = v[i].x * inv * gg.x + bb.x;
        r.y = v[i].y * inv * gg.y + bb.y;
        r.z = v[i].z * inv * gg.z + bb.z;
        r.w = v[i].w * inv * gg.w + bb.w;
        po[lane + i * 32] = r;
        ph[(lane + i * 32) * 2]     = __floats2half2_rn(r.x, r.y);
        ph[(lane + i * 32) * 2 + 1] = __floats2half2_rn(r.z, r.w);
    }
}

// ---------------- final LayerNorm ----------------
__global__ __launch_bounds__(256) void ln_k(
    const float* __restrict__ in, const float* __restrict__ g,
    const float* __restrict__ bt, float* __restrict__ out)
{
    const int row  = blockIdx.x * 8 + (threadIdx.x >> 5);
    const int lane = threadIdx.x & 31;
    const float4* p = (const float4*)(in + (size_t)row * Dc);

    float4 v[8];
    float sum = 0.0f;
#pragma unroll
    for (int i = 0; i < 8; i++) {
        v[i] = p[lane + i * 32];
        sum += v[i].x + v[i].y + v[i].z + v[i].w;
    }
#pragma unroll
    for (int o = 16; o; o >>= 1) sum += __shfl_xor_sync(0xffffffffu, sum, o);
    const float mu = sum * (1.0f / Dc);

    float var = 0.0f;
#pragma unroll
    for (int i = 0; i < 8; i++) {
        v[i].x -= mu; v[i].y -= mu; v[i].z -= mu; v[i].w -= mu;
        var += v[i].x * v[i].x + v[i].y * v[i].y + v[i].z * v[i].z + v[i].w * v[i].w;
    }
#pragma unroll
    for (int o = 16; o; o >>= 1) var += __shfl_xor_sync(0xffffffffu, var, o);
    const float inv = rsqrtf(var * (1.0f / Dc) + 1e-5f);

    float4* po = (float4*)(out + (size_t)row * Dc);
#pragma unroll
    for (int i = 0; i < 8; i++) {
        float4 gg = ((const float4*)g)[lane + i * 32];
        float4 bb = ((const float4*)bt)[lane + i * 32];
        float4 r;
        r.x = v[i].x * inv * gg.x + bb.x;
        r.y = v[i].y * inv * gg.y + bb.y;
        r.z = v[i].z * inv * gg.z + bb.z;
        r.w = v[i].w * inv * gg.w + bb.w;
        po[lane + i * 32] = r;
    }
}

// ---------------- host orchestration ----------------
extern "C" void kernel_launch(void* const* d_in, const int* in_sizes, int n_in,
                              void* d_out, int out_size)
{
    const float* src = (const float*)d_in[0];
    const float* Wq  = (const float*)d_in[1];
    const float* bq  = (const float*)d_in[2];
    const float* Wk  = (const float*)d_in[3];
    const float* bk  = (const float*)d_in[4];
    const float* Wv  = (const float*)d_in[5];
    const float* bv  = (const float*)d_in[6];
    const float* Wo  = (const float*)d_in[7];
    const float* bo  = (const float*)d_in[8];
    const float* W1  = (const float*)d_in[9];
    const float* b1  = (const float*)d_in[10];
    const float* W2  = (const float*)d_in[11];
    const float* b2  = (const float*)d_in[12];
    const float* g1  = (const float*)d_in[13];
    const float* be1 = (const float*)d_in[14];
    const float* g2  = (const float*)d_in[15];
    const float* be2 = (const float*)d_in[16];
    const float* gf  = (const float*)d_in[17];
    const float* bf  = (const float*)d_in[18];

    float *x, *tmp, *tmp2, *pe, *bqkv;
    __half *xh, *qh, *kh, *vh, *oh, *ffh, *wqkvh, *woh, *w1h, *w2h;
    cudaGetSymbolAddress((void**)&x,    g_x);
    cudaGetSymbolAddress((void**)&tmp,  g_tmp);
    cudaGetSymbolAddress((void**)&tmp2, g_tmp2);
    cudaGetSymbolAddress((void**)&pe,   g_pe);
    cudaGetSymbolAddress((void**)&bqkv, g_bqkv);
    cudaGetSymbolAddress((void**)&xh,   g_xh);
    cudaGetSymbolAddress((void**)&qh,   g_qh);
    cudaGetSymbolAddress((void**)&kh,   g_kh);
    cudaGetSymbolAddress((void**)&vh,   g_vh);
    cudaGetSymbolAddress((void**)&oh,   g_oh);
    cudaGetSymbolAddress((void**)&ffh,  g_ffh);
    cudaGetSymbolAddress((void**)&wqkvh,g_wqkv);
    cudaGetSymbolAddress((void**)&woh,  g_wo);
    cudaGetSymbolAddress((void**)&w1h,  g_w1);
    cudaGetSymbolAddress((void**)&w2h,  g_w2);

    cudaFuncSetAttribute(gemm_qkv, cudaFuncAttributeMaxDynamicSharedMemorySize, GEMM_DSM);
    cudaFuncSetAttribute(gemm_g,   cudaFuncAttributeMaxDynamicSharedMemorySize, GEMM_DSM);
    cudaFuncSetAttribute(gemm_s,   cudaFuncAttributeMaxDynamicSharedMemorySize, GEMM_DSM);
    cudaFuncSetAttribute(fa_k,     cudaFuncAttributeMaxDynamicSharedMemorySize, FA_DSM);

    prol_k<<<PROL_BLOCKS, 256>>>(Wq, Wk, Wv, Wo, W1, W2,
                                 wqkvh, woh, w1h, w2h,
                                 src, x, xh, bq, bk, bv, bqkv, pe);

    const int M = Mtot;
    const size_t DD = (size_t)Dc * Dc;
    dim3 gQKV(3 * Dc / 128, M / 128);      // (24, 16)
    dim3 gF(FFc / 128, M / 128);           // (32, 16)
    dim3 gS(Dc / 128, M / 128, 2);         // (8, 16, 2) split-K
    dim3 gFA(Lc / 128, Bc * Hc);           // (8, 32)
    const int gLN = M / 8;                 // 256 blocks

    for (int l = 0; l < NLc; l++) {
        const __half* wqkvl = wqkvh + (size_t)l * 3 * DD;
        const __half* wo = woh + (size_t)l * DD;
        const __half* w1 = w1h + (size_t)l * Dc * FFc;
        const __half* w2 = w2h + (size_t)l * FFc * Dc;

        gemm_qkv<<<gQKV, 256, GEMM_DSM>>>(xh, wqkvl, bqkv + l * 3 * Dc, pe, qh, kh, vh, M, 3 * Dc, Dc);
        fa_k<<<gFA, 256, FA_DSM>>>(qh, kh, vh, oh);

        gemm_s<<<gS, 256, GEMM_DSM>>>(oh, wo, tmp, tmp2, Dc, Dc / 2, Dc);
        lnr_k<<<gLN, 256>>>(tmp, tmp2, x, bo + l * Dc, g1 + l * Dc, be1 + l * Dc, x, xh);

        gemm_g<<<gF, 256, GEMM_DSM>>>(xh, w1, b1 + (size_t)l * FFc, ffh, M, FFc, Dc);
        gemm_s<<<gS, 256, GEMM_DSM>>>(ffh, w2, tmp, tmp2, Dc, FFc / 2, FFc);
        lnr_k<<<gLN, 256>>>(tmp, tmp2, x, b2 + l * Dc, g2 + l * Dc, be2 + l * Dc, x, xh);
    }

    ln_k<<<gLN, 256>>>(x, gf, bf, (float*)d_out);
}